// round 8
// baseline (speedup 1.0000x reference)
#include <cuda_runtime.h>
#include <cstddef>

#define NF 510
#define BB 32
#define HH 4
#define DD 64

// ---------------- scratch (__device__ globals; no allocation allowed) ----------------
__device__ float  g_xt[(size_t)BB*NF*256];   // xt[b][n][h*64+d]
__device__ float  g_si[BB*HH*NF];            // s_i[b][h][n]
__device__ float  g_sj[BB*HH*NF];            // s_j[b][h][n]
__device__ float4 g_cc[(size_t)NF*NF];       // 0.9*(conv3x3(causal, w[:,1]) + bias), [n][m] x 4 heads
__device__ float  g_out[(size_t)BB*NF*DD];   // mean_h(A @ xt)

// ---------------- K1: xt = x @ W   (16320x64 @ 64x256) ----------------
__global__ __launch_bounds__(256) void k_xt(const float* __restrict__ x,
                                            const float* __restrict__ W) {
    __shared__ __align__(16) float xs[16][64];
    int c = threadIdx.x;
    size_t base = (size_t)blockIdx.x * (16 * 64);
#pragma unroll
    for (int i = 0; i < 4; i++) {
        int idx = c + i * 256;
        xs[idx >> 6][idx & 63] = x[base + idx];
    }
    __syncthreads();
    float acc[16];
#pragma unroll
    for (int r = 0; r < 16; r++) acc[r] = 0.f;
    for (int kc = 0; kc < 16; kc++) {
        float w0 = W[(kc * 4 + 0) * 256 + c];
        float w1 = W[(kc * 4 + 1) * 256 + c];
        float w2 = W[(kc * 4 + 2) * 256 + c];
        float w3 = W[(kc * 4 + 3) * 256 + c];
#pragma unroll
        for (int r = 0; r < 16; r++) {
            float4 xv = *(const float4*)&xs[r][kc * 4];
            acc[r] = fmaf(xv.x, w0, acc[r]);
            acc[r] = fmaf(xv.y, w1, acc[r]);
            acc[r] = fmaf(xv.z, w2, acc[r]);
            acc[r] = fmaf(xv.w, w3, acc[r]);
        }
    }
    size_t ob = (size_t)blockIdx.x * (16 * 256);
#pragma unroll
    for (int r = 0; r < 16; r++) g_xt[ob + r * 256 + c] = acc[r];
}

// ---------------- K2: s_i, s_j (one warp per (b,n) row) ----------------
__global__ __launch_bounds__(256) void k_s(const float* __restrict__ attw) {
    __shared__ float aw[512];
    int tid = threadIdx.x;
    aw[tid] = attw[tid];
    aw[tid + 256] = attw[tid + 256];
    __syncthreads();
    int w = tid >> 5, lane = tid & 31;
    int row = blockIdx.x * 8 + w;            // 0..16319
    const float* xr = g_xt + (size_t)row * 256;
    float xv[8];
#pragma unroll
    for (int j = 0; j < 8; j++) xv[j] = xr[lane + 32 * j];
    int b = row / NF, n = row % NF;
#pragma unroll
    for (int h = 0; h < 4; h++) {
        float si = xv[2*h] * aw[h*128 + lane] + xv[2*h+1] * aw[h*128 + 32 + lane];
        float sj = xv[2*h] * aw[h*128 + 64 + lane] + xv[2*h+1] * aw[h*128 + 96 + lane];
#pragma unroll
        for (int o = 16; o; o >>= 1) {
            si += __shfl_xor_sync(0xffffffffu, si, o);
            sj += __shfl_xor_sync(0xffffffffu, sj, o);
        }
        if (!lane) {
            g_si[(b * 4 + h) * NF + n] = si;
            g_sj[(b * 4 + h) * NF + n] = sj;
        }
    }
}

// ---------------- K2b: Cc = 0.9*(conv3x3(causal, w[:,1,:,:]) + bias), batch-invariant ----------------
__global__ __launch_bounds__(512) void k_cc(const float* __restrict__ causal,
                                            const float* __restrict__ cw,
                                            const float* __restrict__ cb) {
    __shared__ float cs[3][512];
    __shared__ float w1s[36];
    __shared__ float cbs[4];
    int m = threadIdx.x, n = blockIdx.x;
    if (m < 36) w1s[m] = 0.9f * cw[(m / 9) * 18 + 9 + (m % 9)];
    if (m < 4)  cbs[m] = 0.9f * cb[m];
#pragma unroll
    for (int ky = 0; ky < 3; ky++) {
        int rr = n + ky - 1;
        if (m < NF) cs[ky][m + 1] = (rr >= 0 && rr < NF) ? causal[rr * NF + m] : 0.f;
        else        cs[ky][m == NF ? 0 : 511] = 0.f;
    }
    __syncthreads();
    if (m < NF) {
        float c[9];
#pragma unroll
        for (int ky = 0; ky < 3; ky++)
#pragma unroll
            for (int kx = 0; kx < 3; kx++) c[ky * 3 + kx] = cs[ky][m + kx];
        float o[4];
#pragma unroll
        for (int h = 0; h < 4; h++) {
            float v = cbs[h];
#pragma unroll
            for (int j = 0; j < 9; j++) v = fmaf(w1s[h * 9 + j], c[j], v);
            o[h] = v;
        }
        g_cc[n * NF + m] = make_float4(o[0], o[1], o[2], o[3]);
    }
}

// ---------------- K3: fused logits (0.1*eva + conv(A_mean) + Cc) + softmax + A write ----------------
// block = (6-row tile, batch), 512 threads; thread = column m, all 4 heads.
__global__ __launch_bounds__(512) void k_attn(const float* __restrict__ cw,
                                              float* __restrict__ Aout) {
    const int R = 6;
    __shared__ float amean[R + 2][512];  // sum_h leaky(si+sj); [rr][0],[rr][511] = zero pad
    __shared__ float si_sh[R + 2][4];
    __shared__ int   rowok[R + 2];
    __shared__ float w0s[36];
    __shared__ float red[16][4];
    __shared__ float bmax[4];
    __shared__ float binv[4];

    int m = threadIdx.x;
    int b = blockIdx.y;
    int r0 = blockIdx.x * R;
    bool mv = m < NF;

    float sj[4];
#pragma unroll
    for (int h = 0; h < 4; h++) sj[h] = mv ? g_sj[(b * 4 + h) * NF + m] : 0.f;

    if (m < (R + 2) * 4) {
        int rr = m >> 2, h = m & 3;
        int row = r0 - 1 + rr;
        int ok = (row >= 0 && row < NF);
        si_sh[rr][h] = ok ? g_si[(b * 4 + h) * NF + row] : 0.f;
        if (h == 0) rowok[rr] = ok;
    }
    // fold 0.9 (A_st weight) * 0.25 (head mean) into channel-0 conv weights
    if (m < 36) w0s[m] = 0.225f * cw[(m / 9) * 18 + (m % 9)];
    __syncthreads();

#pragma unroll
    for (int rr = 0; rr < R + 2; rr++) {
        float v = 0.f;
        if (rowok[rr]) {
#pragma unroll
            for (int h = 0; h < 4; h++) {
                float t = si_sh[rr][h] + sj[h];
                v += fmaxf(t, 0.01f * t);          // leaky-relu
            }
        }
        if (mv) amean[rr][m + 1] = v;
        else    amean[rr][m == NF ? 0 : 511] = 0.f;
    }
    __syncthreads();

    int wid = m >> 5, lane = m & 31;
    for (int r = 0; r < R; r++) {
        int n = r0 + r;
        float lg[4];
        if (mv) {
            float a[9];
#pragma unroll
            for (int ky = 0; ky < 3; ky++)
#pragma unroll
                for (int kx = 0; kx < 3; kx++) a[ky * 3 + kx] = amean[r + ky][m + kx];
            float4 cc = g_cc[n * NF + m];
            float bse[4] = {cc.x, cc.y, cc.z, cc.w};
#pragma unroll
            for (int h = 0; h < 4; h++) {
                float acc = bse[h];
#pragma unroll
                for (int j = 0; j < 9; j++) acc = fmaf(w0s[h * 9 + j], a[j], acc);
                float t = si_sh[r + 1][h] + sj[h];
                lg[h] = fmaf(0.1f, fmaxf(t, 0.01f * t), acc);
            }
        } else {
#pragma unroll
            for (int h = 0; h < 4; h++) lg[h] = -1e30f;
        }
        // block max over m
        float v[4];
#pragma unroll
        for (int h = 0; h < 4; h++) v[h] = lg[h];
#pragma unroll
        for (int o = 16; o; o >>= 1)
#pragma unroll
            for (int h = 0; h < 4; h++) v[h] = fmaxf(v[h], __shfl_xor_sync(0xffffffffu, v[h], o));
        if (!lane)
#pragma unroll
            for (int h = 0; h < 4; h++) red[wid][h] = v[h];
        __syncthreads();
        if (m < 32) {
            float t[4];
#pragma unroll
            for (int h = 0; h < 4; h++) t[h] = (m < 16) ? red[m][h] : -1e30f;
#pragma unroll
            for (int o = 16; o; o >>= 1)
#pragma unroll
                for (int h = 0; h < 4; h++) t[h] = fmaxf(t[h], __shfl_xor_sync(0xffffffffu, t[h], o));
            if (!m)
#pragma unroll
                for (int h = 0; h < 4; h++) bmax[h] = t[h];
        }
        __syncthreads();
        // exp + block sum
        float ex[4];
#pragma unroll
        for (int h = 0; h < 4; h++) ex[h] = mv ? __expf(lg[h] - bmax[h]) : 0.f;
#pragma unroll
        for (int h = 0; h < 4; h++) v[h] = ex[h];
#pragma unroll
        for (int o = 16; o; o >>= 1)
#pragma unroll
            for (int h = 0; h < 4; h++) v[h] += __shfl_xor_sync(0xffffffffu, v[h], o);
        if (!lane)
#pragma unroll
            for (int h = 0; h < 4; h++) red[wid][h] = v[h];
        __syncthreads();
        if (m < 32) {
            float t[4];
#pragma unroll
            for (int h = 0; h < 4; h++) t[h] = (m < 16) ? red[m][h] : 0.f;
#pragma unroll
            for (int o = 16; o; o >>= 1)
#pragma unroll
                for (int h = 0; h < 4; h++) t[h] += __shfl_xor_sync(0xffffffffu, t[h], o);
            if (!m)
#pragma unroll
                for (int h = 0; h < 4; h++) binv[h] = 1.0f / t[h];
        }
        __syncthreads();
        if (mv) {
#pragma unroll
            for (int h = 0; h < 4; h++)
                Aout[((size_t)(b * 4 + h) * NF + n) * NF + m] = ex[h] * binv[h];
        }
        // subsequent red/bmax rewrites are ordered by the syncs above
    }
}

// ---------------- K4: out = 0.25 * sum_h A_h @ xt_h  (per-b SGEMM M=510,N=64,K=4x510) ----------------
// grid (4 row-tiles of 128, 32 batches) = 128 blocks (single wave), 256 thr, 8x4 microtile.
__global__ __launch_bounds__(256) void k_av(const float* __restrict__ A) {
    __shared__ __align__(16) float As[16 * 132];   // [k][row], pitch 132
    __shared__ __align__(16) float Bs[16 * 68];    // [k][col], pitch 68
    int b = blockIdx.y;
    int r0 = blockIdx.x * 128;
    int nvalid = NF - r0; if (nvalid > 128) nvalid = 128;
    int tid = threadIdx.x;
    int tx = tid & 15, ty = tid >> 4;
    float acc[8][4];
#pragma unroll
    for (int i = 0; i < 8; i++)
#pragma unroll
        for (int j = 0; j < 4; j++) acc[i][j] = 0.f;

    for (int h = 0; h < 4; h++) {
        const float* Ab = A + ((size_t)(b * 4 + h) * NF + r0) * NF;
        const float* Xb = g_xt + (size_t)b * NF * 256 + h * 64;
        for (int k0 = 0; k0 < NF; k0 += 16) {
            __syncthreads();
#pragma unroll
            for (int i = 0; i < 8; i++) {
                int row = (tid >> 4) + i * 16;
                int k = tid & 15;
                float v = 0.f;
                if (row < nvalid && k0 + k < NF) v = Ab[(size_t)row * NF + k0 + k];
                As[k * 132 + row] = v;
            }
#pragma unroll
            for (int i = 0; i < 4; i++) {
                int k = (tid >> 6) + i * 4;
                int col = tid & 63;
                float v = 0.f;
                if (k0 + k < NF) v = Xb[(size_t)(k0 + k) * 256 + col];
                Bs[k * 68 + col] = v;
            }
            __syncthreads();
#pragma unroll
            for (int kk = 0; kk < 16; kk++) {
                float4 a0 = *(const float4*)&As[kk * 132 + ty * 8];
                float4 a1 = *(const float4*)&As[kk * 132 + ty * 8 + 4];
                float4 bv = *(const float4*)&Bs[kk * 68 + tx * 4];
                float ar[8] = {a0.x, a0.y, a0.z, a0.w, a1.x, a1.y, a1.z, a1.w};
                float br[4] = {bv.x, bv.y, bv.z, bv.w};
#pragma unroll
                for (int i = 0; i < 8; i++)
#pragma unroll
                    for (int j = 0; j < 4; j++)
                        acc[i][j] = fmaf(ar[i], br[j], acc[i][j]);
            }
        }
    }
#pragma unroll
    for (int i = 0; i < 8; i++) {
        int row = ty * 8 + i;
        if (row < nvalid) {
            float4 o = make_float4(acc[i][0] * 0.25f, acc[i][1] * 0.25f,
                                   acc[i][2] * 0.25f, acc[i][3] * 0.25f);
            *(float4*)&g_out[((size_t)(b * NF) + r0 + row) * 64 + tx * 4] = o;
        }
    }
}

// ---------------- K5: g = out@fcg_w + b, GLU, +x, LayerNorm  (warp per row) ----------------
__global__ __launch_bounds__(256) void k_fin(const float* __restrict__ x,
                                             const float* __restrict__ fw,
                                             const float* __restrict__ fb,
                                             const float* __restrict__ lng,
                                             const float* __restrict__ lnb,
                                             float* __restrict__ y) {
    __shared__ float outs[8][64];
    int tid = threadIdx.x;
    int r0 = blockIdx.x * 8;
#pragma unroll
    for (int i = 0; i < 2; i++) {
        int idx = tid + i * 256;
        outs[idx >> 6][idx & 63] = g_out[(size_t)r0 * 64 + idx];
    }
    __syncthreads();
    int w = tid >> 5, lane = tid & 31;
    int row = r0 + w;
    const float* o = outs[w];
    float a0 = fb[lane], a1 = fb[lane + 32], b0 = fb[64 + lane], b1 = fb[96 + lane];
    for (int k = 0; k < 64; k++) {
        float xo = o[k];
        const float* wr = fw + k * 128;
        a0 = fmaf(xo, wr[lane], a0);
        a1 = fmaf(xo, wr[lane + 32], a1);
        b0 = fmaf(xo, wr[64 + lane], b0);
        b1 = fmaf(xo, wr[96 + lane], b1);
    }
    float g0 = a0 / (1.f + __expf(-b0));
    float g1 = a1 / (1.f + __expf(-b1));
    float y0 = g0 + x[(size_t)row * 64 + lane];
    float y1 = g1 + x[(size_t)row * 64 + lane + 32];
    float s1 = y0 + y1, s2 = y0 * y0 + y1 * y1;
#pragma unroll
    for (int off = 16; off; off >>= 1) {
        s1 += __shfl_xor_sync(0xffffffffu, s1, off);
        s2 += __shfl_xor_sync(0xffffffffu, s2, off);
    }
    float mu = s1 * (1.f / 64.f);
    float var = s2 * (1.f / 64.f) - mu * mu;
    float inv = rsqrtf(var + 1e-5f);
    y[(size_t)row * 64 + lane]      = (y0 - mu) * inv * lng[lane] + lnb[lane];
    y[(size_t)row * 64 + lane + 32] = (y1 - mu) * inv * lng[lane + 32] + lnb[lane + 32];
}

extern "C" void kernel_launch(void* const* d_in, const int* in_sizes, int n_in,
                              void* d_out, int out_size) {
    const float* x      = (const float*)d_in[0];
    const float* causal = (const float*)d_in[1];
    const float* W      = (const float*)d_in[2];
    const float* attw   = (const float*)d_in[3];
    const float* cw     = (const float*)d_in[4];
    const float* cb     = (const float*)d_in[5];
    const float* fcgw   = (const float*)d_in[6];
    const float* fcgb   = (const float*)d_in[7];
    const float* lng    = (const float*)d_in[8];
    const float* lnb    = (const float*)d_in[9];

    float* y = (float*)d_out;                       // y: B*N*D = 1,044,480 floats
    float* A = y + (size_t)BB * NF * DD;            // A: B*H*N*N = 33,292,800 floats

    k_xt  <<<1020, 256>>>(x, W);
    k_s   <<<2040, 256>>>(attw);
    k_cc  <<<510, 512>>>(causal, cw, cb);
    k_attn<<<dim3(85, 32), 512>>>(cw, A);
    k_av  <<<dim3(4, 32), 256>>>(A);
    k_fin <<<2040, 256>>>(x, fcgw, fcgb, lng, lnb, y);
}

// round 9
// speedup vs baseline: 1.7684x; 1.7684x over previous
#include <cuda_runtime.h>
#include <cstddef>

#define NF 510
#define BB 32
#define HH 4
#define DD 64

// ---------------- scratch (__device__ globals; no allocation allowed) ----------------
__device__ float  g_xt[(size_t)BB*NF*256];   // xt[b][n][h*64+d]
__device__ float  g_si[BB*HH*NF];            // s_i[b][h][n]
__device__ float  g_sj[BB*HH*NF];            // s_j[b][h][n]
__device__ float4 g_cc[(size_t)NF*NF];       // 0.9*(conv3x3(causal, w[:,1]) + bias), [n][m] x 4 heads
__device__ float  g_out[(size_t)BB*NF*DD];   // mean_h(A @ xt)

// ---- packed f32x2 helpers (FFMA2: 2 MACs / instruction) ----
__device__ __forceinline__ unsigned long long pk2(float v) {
    unsigned long long r;
    unsigned u = __float_as_uint(v);
    asm("mov.b64 %0, {%1, %1};" : "=l"(r) : "r"(u));
    return r;
}
__device__ __forceinline__ void ffma2(unsigned long long& d, unsigned long long a, unsigned long long b) {
    asm("fma.rn.f32x2 %0, %1, %2, %0;" : "+l"(d) : "l"(a), "l"(b));
}

// ---------------- K1: xt = x @ W   (16320x64 @ 64x256) ----------------
__global__ __launch_bounds__(256) void k_xt(const float* __restrict__ x,
                                            const float* __restrict__ W) {
    __shared__ __align__(16) float xs[16][64];
    int c = threadIdx.x;
    size_t base = (size_t)blockIdx.x * (16 * 64);
#pragma unroll
    for (int i = 0; i < 4; i++) {
        int idx = c + i * 256;
        xs[idx >> 6][idx & 63] = x[base + idx];
    }
    __syncthreads();
    float acc[16];
#pragma unroll
    for (int r = 0; r < 16; r++) acc[r] = 0.f;
    for (int kc = 0; kc < 16; kc++) {
        float w0 = W[(kc * 4 + 0) * 256 + c];
        float w1 = W[(kc * 4 + 1) * 256 + c];
        float w2 = W[(kc * 4 + 2) * 256 + c];
        float w3 = W[(kc * 4 + 3) * 256 + c];
#pragma unroll
        for (int r = 0; r < 16; r++) {
            float4 xv = *(const float4*)&xs[r][kc * 4];
            acc[r] = fmaf(xv.x, w0, acc[r]);
            acc[r] = fmaf(xv.y, w1, acc[r]);
            acc[r] = fmaf(xv.z, w2, acc[r]);
            acc[r] = fmaf(xv.w, w3, acc[r]);
        }
    }
    size_t ob = (size_t)blockIdx.x * (16 * 256);
#pragma unroll
    for (int r = 0; r < 16; r++) g_xt[ob + r * 256 + c] = acc[r];
}

// ---------------- K2: s_i, s_j (one warp per (b,n) row) ----------------
__global__ __launch_bounds__(256) void k_s(const float* __restrict__ attw) {
    __shared__ float aw[512];
    int tid = threadIdx.x;
    aw[tid] = attw[tid];
    aw[tid + 256] = attw[tid + 256];
    __syncthreads();
    int w = tid >> 5, lane = tid & 31;
    int row = blockIdx.x * 8 + w;            // 0..16319
    const float* xr = g_xt + (size_t)row * 256;
    float xv[8];
#pragma unroll
    for (int j = 0; j < 8; j++) xv[j] = xr[lane + 32 * j];
    int b = row / NF, n = row % NF;
#pragma unroll
    for (int h = 0; h < 4; h++) {
        float si = xv[2*h] * aw[h*128 + lane] + xv[2*h+1] * aw[h*128 + 32 + lane];
        float sj = xv[2*h] * aw[h*128 + 64 + lane] + xv[2*h+1] * aw[h*128 + 96 + lane];
#pragma unroll
        for (int o = 16; o; o >>= 1) {
            si += __shfl_xor_sync(0xffffffffu, si, o);
            sj += __shfl_xor_sync(0xffffffffu, sj, o);
        }
        if (!lane) {
            g_si[(b * 4 + h) * NF + n] = si;
            g_sj[(b * 4 + h) * NF + n] = sj;
        }
    }
}

// ---------------- K2b: Cc = 0.9*(conv3x3(causal, w[:,1,:,:]) + bias), batch-invariant ----------------
__global__ __launch_bounds__(512) void k_cc(const float* __restrict__ causal,
                                            const float* __restrict__ cw,
                                            const float* __restrict__ cb) {
    __shared__ float cs[3][512];
    __shared__ float w1s[36];
    __shared__ float cbs[4];
    int m = threadIdx.x, n = blockIdx.x;
    if (m < 36) w1s[m] = 0.9f * cw[(m / 9) * 18 + 9 + (m % 9)];
    if (m < 4)  cbs[m] = 0.9f * cb[m];
#pragma unroll
    for (int ky = 0; ky < 3; ky++) {
        int rr = n + ky - 1;
        if (m < NF) cs[ky][m + 1] = (rr >= 0 && rr < NF) ? causal[rr * NF + m] : 0.f;
        else        cs[ky][m == NF ? 0 : 511] = 0.f;
    }
    __syncthreads();
    if (m < NF) {
        float c[9];
#pragma unroll
        for (int ky = 0; ky < 3; ky++)
#pragma unroll
            for (int kx = 0; kx < 3; kx++) c[ky * 3 + kx] = cs[ky][m + kx];
        float o[4];
#pragma unroll
        for (int h = 0; h < 4; h++) {
            float v = cbs[h];
#pragma unroll
            for (int j = 0; j < 9; j++) v = fmaf(w1s[h * 9 + j], c[j], v);
            o[h] = v;
        }
        g_cc[n * NF + m] = make_float4(o[0], o[1], o[2], o[3]);
    }
}

// ---------------- K3: fused logits + softmax (no max-sub) + A write ----------------
// block = (10-row tile, batch), 512 threads; thread = column m, all 4 heads.
// Register-rotated 3x3 stencil window (3 new LDS per row instead of 9).
__global__ __launch_bounds__(512) void k_attn(const float* __restrict__ cw,
                                              float* __restrict__ Aout) {
    const int R = 10;
    __shared__ float amean[R + 2][512];  // sum_h leaky(si+sj); cols 0/511 = zero pad
    __shared__ float si_sh[R + 2][4];
    __shared__ float w0s[36];
    __shared__ float red[16][4];
    __shared__ float binv[4];

    int m = threadIdx.x;
    int b = blockIdx.y;
    int r0 = blockIdx.x * R;            // 51 tiles * 10 = 510 exactly
    bool mv = m < NF;

    float sj[4];
#pragma unroll
    for (int h = 0; h < 4; h++) sj[h] = mv ? g_sj[(b * 4 + h) * NF + m] : 0.f;

    if (m < (R + 2) * 4) {
        int rr = m >> 2, h = m & 3;
        int row = r0 - 1 + rr;
        si_sh[rr][h] = ((unsigned)row < NF) ? g_si[(b * 4 + h) * NF + row] : 0.f;
    }
    // fold 0.9 (A_st weight) * 0.25 (head mean) into channel-0 conv weights
    if (m < 36) w0s[m] = 0.225f * cw[(m / 9) * 18 + (m % 9)];
    __syncthreads();

#pragma unroll
    for (int rr = 0; rr < R + 2; rr++) {
        int row = r0 - 1 + rr;
        float v = 0.f;
        if ((unsigned)row < NF) {
#pragma unroll
            for (int h = 0; h < 4; h++) {
                float t = si_sh[rr][h] + sj[h];
                v += fmaxf(t, 0.01f * t);          // leaky-relu
            }
        }
        if (mv) amean[rr][m + 1] = v;
        else    amean[rr][m == NF ? 0 : 511] = 0.f;
    }
    __syncthreads();

    int wid = m >> 5, lane = m & 31;
    // preload window rows 0,1 (taps m, m+1, m+2; m <= 509 -> max index 511, always valid)
    float w10 = 0, w11 = 0, w12 = 0, w20 = 0, w21 = 0, w22 = 0;
    if (mv) {
        w10 = amean[0][m]; w11 = amean[0][m + 1]; w12 = amean[0][m + 2];
        w20 = amean[1][m]; w21 = amean[1][m + 1]; w22 = amean[1][m + 2];
    }
    for (int r = 0; r < R; r++) {
        float w00 = w10, w01 = w11, w02 = w12;
        w10 = w20; w11 = w21; w12 = w22;
        float ex[4];
        if (mv) {
            w20 = amean[r + 2][m]; w21 = amean[r + 2][m + 1]; w22 = amean[r + 2][m + 2];
            float4 cc = g_cc[(size_t)(r0 + r) * NF + m];
            float bse[4] = {cc.x, cc.y, cc.z, cc.w};
#pragma unroll
            for (int h = 0; h < 4; h++) {
                const float* wh = &w0s[h * 9];
                float acc = bse[h];
                acc = fmaf(wh[0], w00, acc); acc = fmaf(wh[1], w01, acc); acc = fmaf(wh[2], w02, acc);
                acc = fmaf(wh[3], w10, acc); acc = fmaf(wh[4], w11, acc); acc = fmaf(wh[5], w12, acc);
                acc = fmaf(wh[6], w20, acc); acc = fmaf(wh[7], w21, acc); acc = fmaf(wh[8], w22, acc);
                float t = si_sh[r + 1][h] + sj[h];
                float lg = fmaf(0.1f, fmaxf(t, 0.01f * t), acc);
                ex[h] = __expf(lg);       // logits bounded well below fp32 exp overflow
            }
        } else {
#pragma unroll
            for (int h = 0; h < 4; h++) ex[h] = 0.f;
        }
        // block sum over m (per head); softmax = ex / sum (no max subtraction needed)
        float v[4];
#pragma unroll
        for (int h = 0; h < 4; h++) v[h] = ex[h];
#pragma unroll
        for (int o = 16; o; o >>= 1)
#pragma unroll
            for (int h = 0; h < 4; h++) v[h] += __shfl_xor_sync(0xffffffffu, v[h], o);
        if (!lane)
#pragma unroll
            for (int h = 0; h < 4; h++) red[wid][h] = v[h];
        __syncthreads();
        if (m < 32) {
            float t[4];
#pragma unroll
            for (int h = 0; h < 4; h++) t[h] = (m < 16) ? red[m][h] : 0.f;
#pragma unroll
            for (int o = 16; o; o >>= 1)
#pragma unroll
                for (int h = 0; h < 4; h++) t[h] += __shfl_xor_sync(0xffffffffu, t[h], o);
            if (!m)
#pragma unroll
                for (int h = 0; h < 4; h++) binv[h] = 1.0f / t[h];
        }
        __syncthreads();
        if (mv) {
            int n = r0 + r;
#pragma unroll
            for (int h = 0; h < 4; h++)
                Aout[((size_t)(b * 4 + h) * NF + n) * NF + m] = ex[h] * binv[h];
        }
        // next-iteration red/binv writes are ordered by the two syncs above
    }
}

// ---------------- K4: out = 0.25 * sum_h A_h @ xt_h  (per-b SGEMM, FFMA2) ----------------
// grid (8 row-tiles of 64, 32 batches) = 256 blocks, 256 thr, 4x4 microtile via f32x2 pairs.
__global__ __launch_bounds__(256) void k_av(const float* __restrict__ A) {
    __shared__ __align__(16) float As[16 * 68];   // [k][row], pitch 68
    __shared__ __align__(16) float Bs[16 * 68];   // [k][col], pitch 68
    int b = blockIdx.y;
    int r0 = blockIdx.x * 64;
    int nvalid = NF - r0; if (nvalid > 64) nvalid = 64;
    int tid = threadIdx.x;
    int tx = tid & 15, ty = tid >> 4;             // cols tx*4..+3, rows ty*4..+3
    int la_k = tid & 15, la_r = tid >> 4;         // A loader
    int lb_c = tid & 63, lb_k = tid >> 6;         // B loader

    unsigned long long acc2[2][4];
#pragma unroll
    for (int i = 0; i < 2; i++)
#pragma unroll
        for (int j = 0; j < 4; j++) acc2[i][j] = 0ull;

    float ra[4], rb[4];
    // prologue load (h=0, k0=0)
    {
        const float* Ab = A + ((size_t)(b * 4 + 0) * NF + r0) * NF;
        const float* Xb = g_xt + (size_t)b * NF * 256 + 0 * 64;
#pragma unroll
        for (int i = 0; i < 4; i++) {
            int row = la_r + i * 16;
            ra[i] = (row < nvalid) ? Ab[(size_t)row * NF + la_k] : 0.f;
        }
#pragma unroll
        for (int i = 0; i < 4; i++)
            rb[i] = Xb[(size_t)(lb_k + i * 4) * 256 + lb_c];
    }

    for (int it = 0; it < 128; it++) {
#pragma unroll
        for (int i = 0; i < 4; i++) As[la_k * 68 + la_r + i * 16] = ra[i];
#pragma unroll
        for (int i = 0; i < 4; i++) Bs[(lb_k + i * 4) * 68 + lb_c] = rb[i];
        __syncthreads();
        if (it + 1 < 128) {
            int nit = it + 1;
            int h = nit >> 5, k0 = (nit & 31) * 16;
            const float* Ab = A + ((size_t)(b * 4 + h) * NF + r0) * NF;
            const float* Xb = g_xt + (size_t)b * NF * 256 + h * 64;
#pragma unroll
            for (int i = 0; i < 4; i++) {
                int row = la_r + i * 16;
                ra[i] = (row < nvalid && k0 + la_k < NF) ? Ab[(size_t)row * NF + k0 + la_k] : 0.f;
            }
#pragma unroll
            for (int i = 0; i < 4; i++) {
                int k = lb_k + i * 4;
                rb[i] = (k0 + k < NF) ? Xb[(size_t)(k0 + k) * 256 + lb_c] : 0.f;
            }
        }
        int ty4 = ty * 4;
#pragma unroll
        for (int kk = 0; kk < 16; kk++) {
            unsigned long long a01 = *(const unsigned long long*)&As[kk * 68 + ty4];
            unsigned long long a23 = *(const unsigned long long*)&As[kk * 68 + ty4 + 2];
            float4 bv = *(const float4*)&Bs[kk * 68 + tx * 4];
            unsigned long long b0 = pk2(bv.x), b1 = pk2(bv.y), b2 = pk2(bv.z), b3 = pk2(bv.w);
            ffma2(acc2[0][0], a01, b0); ffma2(acc2[0][1], a01, b1);
            ffma2(acc2[0][2], a01, b2); ffma2(acc2[0][3], a01, b3);
            ffma2(acc2[1][0], a23, b0); ffma2(acc2[1][1], a23, b1);
            ffma2(acc2[1][2], a23, b2); ffma2(acc2[1][3], a23, b3);
        }
        __syncthreads();
    }
    // epilogue: unpack pairs (lo -> row, hi -> row+1), scale by 0.25 (head mean)
#pragma unroll
    for (int i2 = 0; i2 < 2; i2++) {
        union { unsigned long long u; float2 f; } c0, c1, c2, c3;
        c0.u = acc2[i2][0]; c1.u = acc2[i2][1]; c2.u = acc2[i2][2]; c3.u = acc2[i2][3];
        int row0 = ty * 4 + i2 * 2;
        if (row0 < nvalid) {
            float4 o = make_float4(c0.f.x * 0.25f, c1.f.x * 0.25f, c2.f.x * 0.25f, c3.f.x * 0.25f);
            *(float4*)&g_out[((size_t)(b * NF) + r0 + row0) * 64 + tx * 4] = o;
        }
        if (row0 + 1 < nvalid) {
            float4 o = make_float4(c0.f.y * 0.25f, c1.f.y * 0.25f, c2.f.y * 0.25f, c3.f.y * 0.25f);
            *(float4*)&g_out[((size_t)(b * NF) + r0 + row0 + 1) * 64 + tx * 4] = o;
        }
    }
}

// ---------------- K5: g = out@fcg_w + b, GLU, +x, LayerNorm  (warp per row, fw in smem) ----------------
__global__ __launch_bounds__(256) void k_fin(const float* __restrict__ x,
                                             const float* __restrict__ fw,
                                             const float* __restrict__ fb,
                                             const float* __restrict__ lng,
                                             const float* __restrict__ lnb,
                                             float* __restrict__ y) {
    __shared__ __align__(16) float fws[64 * 128];   // 32 KB: full fcg_w
    __shared__ float outs[8][64];
    int tid = threadIdx.x;
    {
        const float4* fw4 = (const float4*)fw;
        float4* fs4 = (float4*)fws;
#pragma unroll
        for (int i = 0; i < 8; i++) fs4[tid + i * 256] = fw4[tid + i * 256];
    }
    int r0 = blockIdx.x * 8;
#pragma unroll
    for (int i = 0; i < 2; i++) {
        int idx = tid + i * 256;
        outs[idx >> 6][idx & 63] = g_out[(size_t)r0 * 64 + idx];
    }
    __syncthreads();
    int w = tid >> 5, lane = tid & 31;
    int row = r0 + w;
    const float* o = outs[w];
    float a0 = fb[lane], a1 = fb[lane + 32], b0 = fb[64 + lane], b1 = fb[96 + lane];
#pragma unroll 4
    for (int k = 0; k < 64; k++) {
        float xo = o[k];
        const float* wr = fws + k * 128;
        a0 = fmaf(xo, wr[lane], a0);
        a1 = fmaf(xo, wr[lane + 32], a1);
        b0 = fmaf(xo, wr[64 + lane], b0);
        b1 = fmaf(xo, wr[96 + lane], b1);
    }
    float g0 = a0 / (1.f + __expf(-b0));
    float g1 = a1 / (1.f + __expf(-b1));
    float y0 = g0 + x[(size_t)row * 64 + lane];
    float y1 = g1 + x[(size_t)row * 64 + lane + 32];
    float s1 = y0 + y1, s2 = y0 * y0 + y1 * y1;
#pragma unroll
    for (int off = 16; off; off >>= 1) {
        s1 += __shfl_xor_sync(0xffffffffu, s1, off);
        s2 += __shfl_xor_sync(0xffffffffu, s2, off);
    }
    float mu = s1 * (1.f / 64.f);
    float var = s2 * (1.f / 64.f) - mu * mu;
    float inv = rsqrtf(var + 1e-5f);
    y[(size_t)row * 64 + lane]      = (y0 - mu) * inv * lng[lane] + lnb[lane];
    y[(size_t)row * 64 + lane + 32] = (y1 - mu) * inv * lng[lane + 32] + lnb[lane + 32];
}

extern "C" void kernel_launch(void* const* d_in, const int* in_sizes, int n_in,
                              void* d_out, int out_size) {
    const float* x      = (const float*)d_in[0];
    const float* causal = (const float*)d_in[1];
    const float* W      = (const float*)d_in[2];
    const float* attw   = (const float*)d_in[3];
    const float* cw     = (const float*)d_in[4];
    const float* cb     = (const float*)d_in[5];
    const float* fcgw   = (const float*)d_in[6];
    const float* fcgb   = (const float*)d_in[7];
    const float* lng    = (const float*)d_in[8];
    const float* lnb    = (const float*)d_in[9];

    float* y = (float*)d_out;                       // y: B*N*D = 1,044,480 floats
    float* A = y + (size_t)BB * NF * DD;            // A: B*H*N*N = 33,292,800 floats

    k_xt  <<<1020, 256>>>(x, W);
    k_s   <<<2040, 256>>>(attw);
    k_cc  <<<510, 512>>>(causal, cw, cb);
    k_attn<<<dim3(51, 32), 512>>>(cw, A);
    k_av  <<<dim3(8, 32), 256>>>(A);
    k_fin <<<2040, 256>>>(x, fcgw, fcgb, lng, lnb, y);
}

// round 11
// speedup vs baseline: 2.2094x; 1.2494x over previous
#include <cuda_runtime.h>
#include <cstddef>

#define NF 510
#define BB 32
#define HH 4
#define DD 64

// ---------------- scratch (__device__ globals; no allocation allowed) ----------------
__device__ float  g_xt[(size_t)BB*NF*256];        // xt[b][n][h*64+d]
__device__ float  g_si[BB*HH*NF];                 // s_i[b][h][n]
__device__ float  g_sj[BB*HH*NF];                 // s_j[b][h][n]
__device__ float4 g_cc[(size_t)NF*NF];            // 0.9*(conv3x3(causal, w[:,1]) + bias)
__device__ float  g_outp[4][(size_t)BB*NF*DD];    // per-head partial A_h @ xt_h

// ---- packed f32x2 helpers (FFMA2: 2 MACs / instruction) ----
__device__ __forceinline__ unsigned long long pk2(float v) {
    unsigned long long r;
    unsigned u = __float_as_uint(v);
    asm("mov.b64 %0, {%1, %1};" : "=l"(r) : "r"(u));
    return r;
}
__device__ __forceinline__ void ffma2(unsigned long long& d, unsigned long long a, unsigned long long b) {
    asm("fma.rn.f32x2 %0, %1, %2, %0;" : "+l"(d) : "l"(a), "l"(b));
}

// ---------------- K1: xt = x @ W   (16320x64 @ 64x256) ----------------
__global__ __launch_bounds__(256) void k_xt(const float* __restrict__ x,
                                            const float* __restrict__ W) {
    __shared__ __align__(16) float xs[16][64];
    int c = threadIdx.x;
    size_t base = (size_t)blockIdx.x * (16 * 64);
#pragma unroll
    for (int i = 0; i < 4; i++) {
        int idx = c + i * 256;
        xs[idx >> 6][idx & 63] = x[base + idx];
    }
    __syncthreads();
    float acc[16];
#pragma unroll
    for (int r = 0; r < 16; r++) acc[r] = 0.f;
    for (int kc = 0; kc < 16; kc++) {
        float w0 = W[(kc * 4 + 0) * 256 + c];
        float w1 = W[(kc * 4 + 1) * 256 + c];
        float w2 = W[(kc * 4 + 2) * 256 + c];
        float w3 = W[(kc * 4 + 3) * 256 + c];
#pragma unroll
        for (int r = 0; r < 16; r++) {
            float4 xv = *(const float4*)&xs[r][kc * 4];
            acc[r] = fmaf(xv.x, w0, acc[r]);
            acc[r] = fmaf(xv.y, w1, acc[r]);
            acc[r] = fmaf(xv.z, w2, acc[r]);
            acc[r] = fmaf(xv.w, w3, acc[r]);
        }
    }
    size_t ob = (size_t)blockIdx.x * (16 * 256);
#pragma unroll
    for (int r = 0; r < 16; r++) g_xt[ob + r * 256 + c] = acc[r];
}

// ---------------- K2: s_i, s_j (one warp per (b,n) row) ----------------
__global__ __launch_bounds__(256) void k_s(const float* __restrict__ attw) {
    __shared__ float aw[512];
    int tid = threadIdx.x;
    aw[tid] = attw[tid];
    aw[tid + 256] = attw[tid + 256];
    __syncthreads();
    int w = tid >> 5, lane = tid & 31;
    int row = blockIdx.x * 8 + w;
    const float* xr = g_xt + (size_t)row * 256;
    float xv[8];
#pragma unroll
    for (int j = 0; j < 8; j++) xv[j] = xr[lane + 32 * j];
    int b = row / NF, n = row % NF;
#pragma unroll
    for (int h = 0; h < 4; h++) {
        float si = xv[2*h] * aw[h*128 + lane] + xv[2*h+1] * aw[h*128 + 32 + lane];
        float sj = xv[2*h] * aw[h*128 + 64 + lane] + xv[2*h+1] * aw[h*128 + 96 + lane];
#pragma unroll
        for (int o = 16; o; o >>= 1) {
            si += __shfl_xor_sync(0xffffffffu, si, o);
            sj += __shfl_xor_sync(0xffffffffu, sj, o);
        }
        if (!lane) {
            g_si[(b * 4 + h) * NF + n] = si;
            g_sj[(b * 4 + h) * NF + n] = sj;
        }
    }
}

// ---------------- K2b: Cc = 0.9*(conv3x3(causal, w[:,1,:,:]) + bias), batch-invariant ----------------
__global__ __launch_bounds__(512) void k_cc(const float* __restrict__ causal,
                                            const float* __restrict__ cw,
                                            const float* __restrict__ cb) {
    __shared__ float cs[3][512];
    __shared__ float w1s[36];
    __shared__ float cbs[4];
    int m = threadIdx.x, n = blockIdx.x;
    if (m < 36) w1s[m] = 0.9f * cw[(m / 9) * 18 + 9 + (m % 9)];
    if (m < 4)  cbs[m] = 0.9f * cb[m];
#pragma unroll
    for (int ky = 0; ky < 3; ky++) {
        int rr = n + ky - 1;
        if (m < NF) cs[ky][m + 1] = (rr >= 0 && rr < NF) ? causal[rr * NF + m] : 0.f;
        else        cs[ky][m == NF ? 0 : 511] = 0.f;
    }
    __syncthreads();
    if (m < NF) {
        float c[9];
#pragma unroll
        for (int ky = 0; ky < 3; ky++)
#pragma unroll
            for (int kx = 0; kx < 3; kx++) c[ky * 3 + kx] = cs[ky][m + kx];
        float o[4];
#pragma unroll
        for (int h = 0; h < 4; h++) {
            float v = cbs[h];
#pragma unroll
            for (int j = 0; j < 9; j++) v = fmaf(w1s[h * 9 + j], c[j], v);
            o[h] = v;
        }
        g_cc[n * NF + m] = make_float4(o[0], o[1], o[2], o[3]);
    }
}

// ---------------- K3: fused logits + softmax (no max-sub) + A write, row PAIRS ----------------
// block = (10-row tile, batch), 512 threads (2 blocks/SM forced); thread = column m, all 4 heads.
__global__ __launch_bounds__(512, 2) void k_attn(const float* __restrict__ cw,
                                                 float* __restrict__ Aout) {
    const int R = 10;
    __shared__ float amean[R + 2][512];  // sum_h leaky(si+sj); cols 0/511 = zero pad
    __shared__ float si_sh[R + 2][4];
    __shared__ float w0s[36];
    __shared__ float red[16][8];
    __shared__ float binv[8];

    int m = threadIdx.x;
    int b = blockIdx.y;
    int r0 = blockIdx.x * R;            // 51 tiles * 10 = 510 exactly
    bool mv = m < NF;

    float sj[4];
#pragma unroll
    for (int h = 0; h < 4; h++) sj[h] = mv ? g_sj[(b * 4 + h) * NF + m] : 0.f;

    if (m < (R + 2) * 4) {
        int rr = m >> 2, h = m & 3;
        int row = r0 - 1 + rr;
        si_sh[rr][h] = ((unsigned)row < NF) ? g_si[(b * 4 + h) * NF + row] : 0.f;
    }
    if (m < 36) w0s[m] = 0.225f * cw[(m / 9) * 18 + (m % 9)];  // 0.9 * 0.25 folded
    __syncthreads();

#pragma unroll
    for (int rr = 0; rr < R + 2; rr++) {
        int row = r0 - 1 + rr;
        float v = 0.f;
        if ((unsigned)row < NF) {
#pragma unroll
            for (int h = 0; h < 4; h++) {
                float t = si_sh[rr][h] + sj[h];
                v += fmaxf(t, 0.01f * t);
            }
        }
        if (mv) amean[rr][m + 1] = v;
        else    amean[rr][m == NF ? 0 : 511] = 0.f;
    }
    __syncthreads();

    int wid = m >> 5, lane = m & 31;
    // rolling 4-row window of the stencil input (taps m, m+1, m+2; max idx 511 valid)
    float w00=0,w01=0,w02=0, w10=0,w11=0,w12=0, w20=0,w21=0,w22=0, w30=0,w31=0,w32=0;
    if (mv) {
        w00=amean[0][m]; w01=amean[0][m+1]; w02=amean[0][m+2];
        w10=amean[1][m]; w11=amean[1][m+1]; w12=amean[1][m+2];
        w20=amean[2][m]; w21=amean[2][m+1]; w22=amean[2][m+2];
        w30=amean[3][m]; w31=amean[3][m+1]; w32=amean[3][m+2];
    }
    for (int p = 0; p < R / 2; p++) {
        int r = 2 * p;
        float ex[8];
        if (mv) {
            float4 cc0 = g_cc[(size_t)(r0 + r) * NF + m];
            float4 cc1 = g_cc[(size_t)(r0 + r + 1) * NF + m];
            float bse0[4] = {cc0.x, cc0.y, cc0.z, cc0.w};
            float bse1[4] = {cc1.x, cc1.y, cc1.z, cc1.w};
#pragma unroll
            for (int h = 0; h < 4; h++) {
                const float* wh = &w0s[h * 9];
                float a0 = bse0[h];
                a0 = fmaf(wh[0], w00, a0); a0 = fmaf(wh[1], w01, a0); a0 = fmaf(wh[2], w02, a0);
                a0 = fmaf(wh[3], w10, a0); a0 = fmaf(wh[4], w11, a0); a0 = fmaf(wh[5], w12, a0);
                a0 = fmaf(wh[6], w20, a0); a0 = fmaf(wh[7], w21, a0); a0 = fmaf(wh[8], w22, a0);
                float a1 = bse1[h];
                a1 = fmaf(wh[0], w10, a1); a1 = fmaf(wh[1], w11, a1); a1 = fmaf(wh[2], w12, a1);
                a1 = fmaf(wh[3], w20, a1); a1 = fmaf(wh[4], w21, a1); a1 = fmaf(wh[5], w22, a1);
                a1 = fmaf(wh[6], w30, a1); a1 = fmaf(wh[7], w31, a1); a1 = fmaf(wh[8], w32, a1);
                float t0 = si_sh[r + 1][h] + sj[h];
                float t1 = si_sh[r + 2][h] + sj[h];
                ex[h]     = __expf(fmaf(0.1f, fmaxf(t0, 0.01f * t0), a0));
                ex[4 + h] = __expf(fmaf(0.1f, fmaxf(t1, 0.01f * t1), a1));
            }
        } else {
#pragma unroll
            for (int q = 0; q < 8; q++) ex[q] = 0.f;
        }
        // block sum over m for 8 (head,row) pairs
        float v[8];
#pragma unroll
        for (int q = 0; q < 8; q++) v[q] = ex[q];
#pragma unroll
        for (int o = 16; o; o >>= 1)
#pragma unroll
            for (int q = 0; q < 8; q++) v[q] += __shfl_xor_sync(0xffffffffu, v[q], o);
        if (!lane)
#pragma unroll
            for (int q = 0; q < 8; q++) red[wid][q] = v[q];
        __syncthreads();
        if (m < 32) {
            float t[8];
#pragma unroll
            for (int q = 0; q < 8; q++) t[q] = (m < 16) ? red[m][q] : 0.f;
#pragma unroll
            for (int o = 16; o; o >>= 1)
#pragma unroll
                for (int q = 0; q < 8; q++) t[q] += __shfl_xor_sync(0xffffffffu, t[q], o);
            if (!m)
#pragma unroll
                for (int q = 0; q < 8; q++) binv[q] = 1.0f / t[q];
        }
        __syncthreads();
        if (mv) {
#pragma unroll
            for (int h = 0; h < 4; h++) {
                Aout[((size_t)(b * 4 + h) * NF + r0 + r) * NF + m]     = ex[h] * binv[h];
                Aout[((size_t)(b * 4 + h) * NF + r0 + r + 1) * NF + m] = ex[4 + h] * binv[4 + h];
            }
        }
        if (p < R / 2 - 1 && mv) {
            w00 = w20; w01 = w21; w02 = w22;
            w10 = w30; w11 = w31; w12 = w32;
            w20 = amean[r + 4][m]; w21 = amean[r + 4][m + 1]; w22 = amean[r + 4][m + 2];
            w30 = amean[r + 5][m]; w31 = amean[r + 5][m + 1]; w32 = amean[r + 5][m + 2];
        }
    }
}

// ---------------- K4: per-head partial = A_h @ xt_h  (tile 128x64, 8x8 microtile, FFMA2) ----------------
// grid (4 row-tiles, 32 batches, 4 heads) = 512 blocks, 128 threads.
__global__ __launch_bounds__(128) void k_av(const float* __restrict__ A) {
    __shared__ __align__(16) float As[16 * 132];   // [k][row], pitch 132 (528B, 16B-mult)
    __shared__ __align__(16) float Bs[16 * 68];    // [k][col], pitch 68  (272B, 16B-mult)
    int b = blockIdx.y;
    int h = blockIdx.z;
    int r0 = blockIdx.x * 128;
    int nvalid = NF - r0; if (nvalid > 128) nvalid = 128;
    int tid = threadIdx.x;
    int tx = tid & 7, ty = tid >> 3;               // cols tx*8..+7, rows ty*8..+7
    int la_k = tid & 15, la_r0 = (tid >> 4) * 16;  // A loader: 16 rows each
    int lb_c = tid & 63, lb_k0 = (tid >> 6) * 8;   // B loader: 8 ks each

    const float* Ab = A + ((size_t)(b * 4 + h) * NF + r0) * NF;
    const float* Xb = g_xt + (size_t)b * NF * 256 + h * 64;

    unsigned long long acc2[4][8];
#pragma unroll
    for (int i = 0; i < 4; i++)
#pragma unroll
        for (int j = 0; j < 8; j++) acc2[i][j] = 0ull;

    float ra[16], rb[8];
    // prologue (k0 = 0)
#pragma unroll
    for (int i = 0; i < 16; i++) {
        int row = la_r0 + i;
        ra[i] = (row < nvalid) ? Ab[(size_t)row * NF + la_k] : 0.f;
    }
#pragma unroll
    for (int i = 0; i < 8; i++)
        rb[i] = Xb[(size_t)(lb_k0 + i) * 256 + lb_c];

    for (int it = 0; it < 32; it++) {
#pragma unroll
        for (int i = 0; i < 16; i++) As[la_k * 132 + la_r0 + i] = ra[i];
#pragma unroll
        for (int i = 0; i < 8; i++) Bs[(lb_k0 + i) * 68 + lb_c] = rb[i];
        __syncthreads();
        if (it + 1 < 32) {
            int k0 = (it + 1) * 16;
#pragma unroll
            for (int i = 0; i < 16; i++) {
                int row = la_r0 + i;
                ra[i] = (row < nvalid && k0 + la_k < NF) ? Ab[(size_t)row * NF + k0 + la_k] : 0.f;
            }
#pragma unroll
            for (int i = 0; i < 8; i++) {
                int k = k0 + lb_k0 + i;
                rb[i] = (k < NF) ? Xb[(size_t)k * 256 + lb_c] : 0.f;
            }
        }
        int ty8 = ty * 8, tx8 = tx * 8;
#pragma unroll
        for (int kk = 0; kk < 16; kk++) {
            ulonglong2 aA = *(const ulonglong2*)&As[kk * 132 + ty8];      // rows 0-1, 2-3
            ulonglong2 aB = *(const ulonglong2*)&As[kk * 132 + ty8 + 4];  // rows 4-5, 6-7
            float4 bv0 = *(const float4*)&Bs[kk * 68 + tx8];
            float4 bv1 = *(const float4*)&Bs[kk * 68 + tx8 + 4];
            unsigned long long bp[8] = {pk2(bv0.x), pk2(bv0.y), pk2(bv0.z), pk2(bv0.w),
                                        pk2(bv1.x), pk2(bv1.y), pk2(bv1.z), pk2(bv1.w)};
#pragma unroll
            for (int c = 0; c < 8; c++) {
                ffma2(acc2[0][c], aA.x, bp[c]);
                ffma2(acc2[1][c], aA.y, bp[c]);
                ffma2(acc2[2][c], aB.x, bp[c]);
                ffma2(acc2[3][c], aB.y, bp[c]);
            }
        }
        __syncthreads();
    }
    // epilogue: raw head-partial sums (0.25 scale applied in k_fin)
    float* outp = g_outp[h];
#pragma unroll
    for (int j = 0; j < 4; j++) {
        union { unsigned long long u; float2 f; } cc[8];
#pragma unroll
        for (int c = 0; c < 8; c++) cc[c].u = acc2[j][c];
        int row0 = ty * 8 + 2 * j;
        if (row0 < nvalid) {
            size_t base = ((size_t)(b * NF) + r0 + row0) * 64 + tx * 8;
            *(float4*)&outp[base]     = make_float4(cc[0].f.x, cc[1].f.x, cc[2].f.x, cc[3].f.x);
            *(float4*)&outp[base + 4] = make_float4(cc[4].f.x, cc[5].f.x, cc[6].f.x, cc[7].f.x);
        }
        if (row0 + 1 < nvalid) {
            size_t base = ((size_t)(b * NF) + r0 + row0 + 1) * 64 + tx * 8;
            *(float4*)&outp[base]     = make_float4(cc[0].f.y, cc[1].f.y, cc[2].f.y, cc[3].f.y);
            *(float4*)&outp[base + 4] = make_float4(cc[4].f.y, cc[5].f.y, cc[6].f.y, cc[7].f.y);
        }
    }
}

// ---------------- K5: g = out@fcg_w + b, GLU, +x, LayerNorm  (warp per row, fw in smem) ----------------
__global__ __launch_bounds__(256) void k_fin(const float* __restrict__ x,
                                             const float* __restrict__ fw,
                                             const float* __restrict__ fb,
                                             const float* __restrict__ lng,
                                             const float* __restrict__ lnb,
                                             float* __restrict__ y) {
    __shared__ __align__(16) float fws[64 * 128];   // 32 KB: full fcg_w
    __shared__ float outs[8][64];
    int tid = threadIdx.x;
    {
        const float4* fw4 = (const float4*)fw;
        float4* fs4 = (float4*)fws;
#pragma unroll
        for (int i = 0; i < 8; i++) fs4[tid + i * 256] = fw4[tid + i * 256];
    }
    int r0 = blockIdx.x * 8;
#pragma unroll
    for (int i = 0; i < 2; i++) {
        int idx = tid + i * 256;
        size_t g = (size_t)r0 * 64 + idx;
        outs[idx >> 6][idx & 63] = 0.25f * (g_outp[0][g] + g_outp[1][g] + g_outp[2][g] + g_outp[3][g]);
    }
    __syncthreads();
    int w = tid >> 5, lane = tid & 31;
    int row = r0 + w;
    const float* o = outs[w];
    float a0 = fb[lane], a1 = fb[lane + 32], b0 = fb[64 + lane], b1 = fb[96 + lane];
#pragma unroll 4
    for (int k = 0; k < 64; k++) {
        float xo = o[k];
        const float* wr = fws + k * 128;
        a0 = fmaf(xo, wr[lane], a0);
        a1 = fmaf(xo, wr[lane + 32], a1);
        b0 = fmaf(xo, wr[64 + lane], b0);
        b1 = fmaf(xo, wr[96 + lane], b1);
    }
    float g0 = a0 / (1.f + __expf(-b0));
    float g1 = a1 / (1.f + __expf(-b1));
    float y0 = g0 + x[(size_t)row * 64 + lane];
    float y1 = g1 + x[(size_t)row * 64 + lane + 32];
    float s1 = y0 + y1, s2 = y0 * y0 + y1 * y1;
#pragma unroll
    for (int off = 16; off; off >>= 1) {
        s1 += __shfl_xor_sync(0xffffffffu, s1, off);
        s2 += __shfl_xor_sync(0xffffffffu, s2, off);
    }
    float mu = s1 * (1.f / 64.f);
    float var = s2 * (1.f / 64.f) - mu * mu;
    float inv = rsqrtf(var + 1e-5f);
    y[(size_t)row * 64 + lane]      = (y0 - mu) * inv * lng[lane] + lnb[lane];
    y[(size_t)row * 64 + lane + 32] = (y1 - mu) * inv * lng[lane + 32] + lnb[lane + 32];
}

extern "C" void kernel_launch(void* const* d_in, const int* in_sizes, int n_in,
                              void* d_out, int out_size) {
    const float* x      = (const float*)d_in[0];
    const float* causal = (const float*)d_in[1];
    const float* W      = (const float*)d_in[2];
    const float* attw   = (const float*)d_in[3];
    const float* cw     = (const float*)d_in[4];
    const float* cb     = (const float*)d_in[5];
    const float* fcgw   = (const float*)d_in[6];
    const float* fcgb   = (const float*)d_in[7];
    const float* lng    = (const float*)d_in[8];
    const float* lnb    = (const float*)d_in[9];

    float* y = (float*)d_out;                       // y: B*N*D
    float* A = y + (size_t)BB * NF * DD;            // A: B*H*N*N

    k_xt  <<<1020, 256>>>(x, W);
    k_s   <<<2040, 256>>>(attw);
    k_cc  <<<510, 512>>>(causal, cw, cb);
    k_attn<<<dim3(51, 32), 512>>>(cw, A);
    k_av  <<<dim3(4, 32, 4), 128>>>(A);
    k_fin <<<2040, 256>>>(x, fcgw, fcgb, lng, lnb, y);
}

// round 12
// speedup vs baseline: 2.2505x; 1.0186x over previous
#include <cuda_runtime.h>
#include <cstddef>

#define NF 510
#define BB 32
#define HH 4
#define DD 64

// ---------------- scratch (__device__ globals; no allocation allowed) ----------------
__device__ float  g_xt[(size_t)BB*NF*256];        // xt[b][n][h*64+d]
__device__ float  g_si[BB*HH*NF];                 // s_i[b][h][n]
__device__ float  g_sj[BB*HH*NF];                 // s_j[b][h][n]
__device__ float4 g_cc[(size_t)NF*NF];            // 0.9*(conv3x3(causal, w[:,1]) + bias)
__device__ float  g_outp[4][(size_t)BB*NF*DD];    // per-head partial A_h @ xt_h

// ---- packed f32x2 helpers (FFMA2: 2 MACs / instruction) ----
__device__ __forceinline__ unsigned long long pk2(float v) {
    unsigned long long r;
    unsigned u = __float_as_uint(v);
    asm("mov.b64 %0, {%1, %1};" : "=l"(r) : "r"(u));
    return r;
}
__device__ __forceinline__ void ffma2(unsigned long long& d, unsigned long long a, unsigned long long b) {
    asm("fma.rn.f32x2 %0, %1, %2, %0;" : "+l"(d) : "l"(a), "l"(b));
}

// ---------------- K1: xt = x @ W   (16320x64 @ 64x256) ----------------
__global__ __launch_bounds__(256) void k_xt(const float* __restrict__ x,
                                            const float* __restrict__ W) {
    __shared__ __align__(16) float xs[16][64];
    int c = threadIdx.x;
    size_t base = (size_t)blockIdx.x * (16 * 64);
#pragma unroll
    for (int i = 0; i < 4; i++) {
        int idx = c + i * 256;
        xs[idx >> 6][idx & 63] = x[base + idx];
    }
    __syncthreads();
    float acc[16];
#pragma unroll
    for (int r = 0; r < 16; r++) acc[r] = 0.f;
    for (int kc = 0; kc < 16; kc++) {
        float w0 = W[(kc * 4 + 0) * 256 + c];
        float w1 = W[(kc * 4 + 1) * 256 + c];
        float w2 = W[(kc * 4 + 2) * 256 + c];
        float w3 = W[(kc * 4 + 3) * 256 + c];
#pragma unroll
        for (int r = 0; r < 16; r++) {
            float4 xv = *(const float4*)&xs[r][kc * 4];
            acc[r] = fmaf(xv.x, w0, acc[r]);
            acc[r] = fmaf(xv.y, w1, acc[r]);
            acc[r] = fmaf(xv.z, w2, acc[r]);
            acc[r] = fmaf(xv.w, w3, acc[r]);
        }
    }
    size_t ob = (size_t)blockIdx.x * (16 * 256);
#pragma unroll
    for (int r = 0; r < 16; r++) g_xt[ob + r * 256 + c] = acc[r];
}

// ---------------- K2: s_i, s_j (one warp per (b,n) row) ----------------
__global__ __launch_bounds__(256) void k_s(const float* __restrict__ attw) {
    __shared__ float aw[512];
    int tid = threadIdx.x;
    aw[tid] = attw[tid];
    aw[tid + 256] = attw[tid + 256];
    __syncthreads();
    int w = tid >> 5, lane = tid & 31;
    int row = blockIdx.x * 8 + w;
    const float* xr = g_xt + (size_t)row * 256;
    float xv[8];
#pragma unroll
    for (int j = 0; j < 8; j++) xv[j] = xr[lane + 32 * j];
    int b = row / NF, n = row % NF;
#pragma unroll
    for (int h = 0; h < 4; h++) {
        float si = xv[2*h] * aw[h*128 + lane] + xv[2*h+1] * aw[h*128 + 32 + lane];
        float sj = xv[2*h] * aw[h*128 + 64 + lane] + xv[2*h+1] * aw[h*128 + 96 + lane];
#pragma unroll
        for (int o = 16; o; o >>= 1) {
            si += __shfl_xor_sync(0xffffffffu, si, o);
            sj += __shfl_xor_sync(0xffffffffu, sj, o);
        }
        if (!lane) {
            g_si[(b * 4 + h) * NF + n] = si;
            g_sj[(b * 4 + h) * NF + n] = sj;
        }
    }
}

// ---------------- K2b: Cc = 0.9*(conv3x3(causal, w[:,1,:,:]) + bias), batch-invariant ----------------
__global__ __launch_bounds__(512) void k_cc(const float* __restrict__ causal,
                                            const float* __restrict__ cw,
                                            const float* __restrict__ cb) {
    __shared__ float cs[3][512];
    __shared__ float w1s[36];
    __shared__ float cbs[4];
    int m = threadIdx.x, n = blockIdx.x;
    if (m < 36) w1s[m] = 0.9f * cw[(m / 9) * 18 + 9 + (m % 9)];
    if (m < 4)  cbs[m] = 0.9f * cb[m];
#pragma unroll
    for (int ky = 0; ky < 3; ky++) {
        int rr = n + ky - 1;
        if (m < NF) cs[ky][m + 1] = (rr >= 0 && rr < NF) ? causal[rr * NF + m] : 0.f;
        else        cs[ky][m == NF ? 0 : 511] = 0.f;
    }
    __syncthreads();
    if (m < NF) {
        float c[9];
#pragma unroll
        for (int ky = 0; ky < 3; ky++)
#pragma unroll
            for (int kx = 0; kx < 3; kx++) c[ky * 3 + kx] = cs[ky][m + kx];
        float o[4];
#pragma unroll
        for (int h = 0; h < 4; h++) {
            float v = cbs[h];
#pragma unroll
            for (int j = 0; j < 9; j++) v = fmaf(w1s[h * 9 + j], c[j], v);
            o[h] = v;
        }
        g_cc[n * NF + m] = make_float4(o[0], o[1], o[2], o[3]);
    }
}

// ---------------- K3: warp-per-row fused logits + softmax + A write (no block barriers in loop) ----
// block = 512 threads = 16 warps = 16 rows; grid (32 tiles, 32 batches).
__global__ __launch_bounds__(512, 2) void k_attn(const float* __restrict__ cw,
                                                 float* __restrict__ Aout) {
    __shared__ float amean[18][520];   // conv input rows r0-1 .. r0+16; col = m+1; pads zeroed
    __shared__ float sjs[4][512];      // s_j per head (cols 510,511 = 0)
    __shared__ float sis[18][4];       // s_i for rows r0-1 .. r0+16
    __shared__ float w0s[36];

    int tid = threadIdx.x;
    int b = blockIdx.y;
    int r0 = blockIdx.x * 16;
    int wid = tid >> 5, lane = tid & 31;

#pragma unroll
    for (int h = 0; h < 4; h++)
        sjs[h][tid] = (tid < NF) ? g_sj[(b * 4 + h) * NF + tid] : 0.f;
    if (tid < 72) {
        int rr = tid >> 2, h = tid & 3;
        int row = r0 - 1 + rr;
        sis[rr][h] = ((unsigned)row < NF) ? g_si[(b * 4 + h) * NF + row] : 0.f;
    }
    if (tid < 36) w0s[tid] = 0.225f * cw[(tid / 9) * 18 + (tid % 9)];  // 0.9 * 0.25 folded
    __syncthreads();

    // build amean: thread tid owns column tid+1 (= m index tid)
    {
        float sjl[4];
#pragma unroll
        for (int h = 0; h < 4; h++) sjl[h] = sjs[h][tid];
        bool mok = tid < NF;
#pragma unroll
        for (int rr = 0; rr < 18; rr++) {
            int row = r0 - 1 + rr;
            float v = 0.f;
            if (mok && (unsigned)row < NF) {
#pragma unroll
                for (int h = 0; h < 4; h++) {
                    float t = sis[rr][h] + sjl[h];
                    v += fmaxf(t, 0.01f * t);
                }
            }
            amean[rr][tid + 1] = v;
        }
        if (tid < 18) { amean[tid][0] = 0.f; amean[tid][513] = 0.f; }
    }
    __syncthreads();   // last barrier

    int n = r0 + wid;
    if (n >= NF) return;

    float si[4];
#pragma unroll
    for (int h = 0; h < 4; h++) si[h] = sis[wid + 1][h];

    size_t aobase = ((size_t)(b * 4) * NF + n) * NF;   // + h*NF*NF + m
    const size_t hstr = (size_t)NF * NF;
    float sum0 = 0.f, sum1 = 0.f, sum2 = 0.f, sum3 = 0.f;

#pragma unroll 4
    for (int c = 0; c < 16; c++) {
        int m = c * 32 + lane;
        bool mval = m < NF;
        // 3x3 stencil taps: amean[wid+ky][m+kx]
        float t00 = amean[wid][m],     t01 = amean[wid][m + 1],     t02 = amean[wid][m + 2];
        float t10 = amean[wid + 1][m], t11 = amean[wid + 1][m + 1], t12 = amean[wid + 1][m + 2];
        float t20 = amean[wid + 2][m], t21 = amean[wid + 2][m + 1], t22 = amean[wid + 2][m + 2];
        float4 ccv = make_float4(0.f, 0.f, 0.f, 0.f);
        if (mval) ccv = g_cc[(size_t)n * NF + m];
        float bse[4] = {ccv.x, ccv.y, ccv.z, ccv.w};
        float e[4];
#pragma unroll
        for (int h = 0; h < 4; h++) {
            const float* wh = &w0s[h * 9];
            float acc = bse[h];
            acc = fmaf(wh[0], t00, acc); acc = fmaf(wh[1], t01, acc); acc = fmaf(wh[2], t02, acc);
            acc = fmaf(wh[3], t10, acc); acc = fmaf(wh[4], t11, acc); acc = fmaf(wh[5], t12, acc);
            acc = fmaf(wh[6], t20, acc); acc = fmaf(wh[7], t21, acc); acc = fmaf(wh[8], t22, acc);
            float tt = si[h] + sjs[h][m];
            float lg = fmaf(0.1f, fmaxf(tt, 0.01f * tt), acc);
            e[h] = mval ? __expf(lg) : 0.f;   // logits bounded far below fp32 exp overflow
        }
        sum0 += e[0]; sum1 += e[1]; sum2 += e[2]; sum3 += e[3];
        if (mval) {
            Aout[aobase + m]            = e[0];
            Aout[aobase + hstr + m]     = e[1];
            Aout[aobase + 2 * hstr + m] = e[2];
            Aout[aobase + 3 * hstr + m] = e[3];
        }
    }
    // warp-private softmax denominators
#pragma unroll
    for (int o = 16; o; o >>= 1) {
        sum0 += __shfl_xor_sync(0xffffffffu, sum0, o);
        sum1 += __shfl_xor_sync(0xffffffffu, sum1, o);
        sum2 += __shfl_xor_sync(0xffffffffu, sum2, o);
        sum3 += __shfl_xor_sync(0xffffffffu, sum3, o);
    }
    float i0 = 1.0f / sum0, i1 = 1.0f / sum1, i2 = 1.0f / sum2, i3 = 1.0f / sum3;
    // pass 2: normalize in place (L1-hot, same-thread RMW)
#pragma unroll 4
    for (int c = 0; c < 16; c++) {
        int m = c * 32 + lane;
        if (m < NF) {
            Aout[aobase + m]            *= i0;
            Aout[aobase + hstr + m]     *= i1;
            Aout[aobase + 2 * hstr + m] *= i2;
            Aout[aobase + 3 * hstr + m] *= i3;
        }
    }
}

// ---------------- K4: per-head partial = A_h @ xt_h  (tile 128x64, 8x8 microtile, FFMA2) ----------------
// grid (4 row-tiles, 32 batches, 4 heads) = 512 blocks, 128 threads.
__global__ __launch_bounds__(128) void k_av(const float* __restrict__ A) {
    __shared__ __align__(16) float As[16 * 132];   // [k][row], pitch 132
    __shared__ __align__(16) float Bs[16 * 68];    // [k][col], pitch 68
    int b = blockIdx.y;
    int h = blockIdx.z;
    int r0 = blockIdx.x * 128;
    int nvalid = NF - r0; if (nvalid > 128) nvalid = 128;
    int tid = threadIdx.x;
    int tx = tid & 7, ty = tid >> 3;
    int la_k = tid & 15, la_r0 = (tid >> 4) * 16;
    int lb_c = tid & 63, lb_k0 = (tid >> 6) * 8;

    const float* Ab = A + ((size_t)(b * 4 + h) * NF + r0) * NF;
    const float* Xb = g_xt + (size_t)b * NF * 256 + h * 64;

    unsigned long long acc2[4][8];
#pragma unroll
    for (int i = 0; i < 4; i++)
#pragma unroll
        for (int j = 0; j < 8; j++) acc2[i][j] = 0ull;

    float ra[16], rb[8];
#pragma unroll
    for (int i = 0; i < 16; i++) {
        int row = la_r0 + i;
        ra[i] = (row < nvalid) ? Ab[(size_t)row * NF + la_k] : 0.f;
    }
#pragma unroll
    for (int i = 0; i < 8; i++)
        rb[i] = Xb[(size_t)(lb_k0 + i) * 256 + lb_c];

    for (int it = 0; it < 32; it++) {
#pragma unroll
        for (int i = 0; i < 16; i++) As[la_k * 132 + la_r0 + i] = ra[i];
#pragma unroll
        for (int i = 0; i < 8; i++) Bs[(lb_k0 + i) * 68 + lb_c] = rb[i];
        __syncthreads();
        if (it + 1 < 32) {
            int k0 = (it + 1) * 16;
#pragma unroll
            for (int i = 0; i < 16; i++) {
                int row = la_r0 + i;
                ra[i] = (row < nvalid && k0 + la_k < NF) ? Ab[(size_t)row * NF + k0 + la_k] : 0.f;
            }
#pragma unroll
            for (int i = 0; i < 8; i++) {
                int k = k0 + lb_k0 + i;
                rb[i] = (k < NF) ? Xb[(size_t)k * 256 + lb_c] : 0.f;
            }
        }
        int ty8 = ty * 8, tx8 = tx * 8;
#pragma unroll
        for (int kk = 0; kk < 16; kk++) {
            ulonglong2 aA = *(const ulonglong2*)&As[kk * 132 + ty8];
            ulonglong2 aB = *(const ulonglong2*)&As[kk * 132 + ty8 + 4];
            float4 bv0 = *(const float4*)&Bs[kk * 68 + tx8];
            float4 bv1 = *(const float4*)&Bs[kk * 68 + tx8 + 4];
            unsigned long long bp[8] = {pk2(bv0.x), pk2(bv0.y), pk2(bv0.z), pk2(bv0.w),
                                        pk2(bv1.x), pk2(bv1.y), pk2(bv1.z), pk2(bv1.w)};
#pragma unroll
            for (int c = 0; c < 8; c++) {
                ffma2(acc2[0][c], aA.x, bp[c]);
                ffma2(acc2[1][c], aA.y, bp[c]);
                ffma2(acc2[2][c], aB.x, bp[c]);
                ffma2(acc2[3][c], aB.y, bp[c]);
            }
        }
        __syncthreads();
    }
    float* outp = g_outp[h];
#pragma unroll
    for (int j = 0; j < 4; j++) {
        union { unsigned long long u; float2 f; } cc[8];
#pragma unroll
        for (int c = 0; c < 8; c++) cc[c].u = acc2[j][c];
        int row0 = ty * 8 + 2 * j;
        if (row0 < nvalid) {
            size_t base = ((size_t)(b * NF) + r0 + row0) * 64 + tx * 8;
            *(float4*)&outp[base]     = make_float4(cc[0].f.x, cc[1].f.x, cc[2].f.x, cc[3].f.x);
            *(float4*)&outp[base + 4] = make_float4(cc[4].f.x, cc[5].f.x, cc[6].f.x, cc[7].f.x);
        }
        if (row0 + 1 < nvalid) {
            size_t base = ((size_t)(b * NF) + r0 + row0 + 1) * 64 + tx * 8;
            *(float4*)&outp[base]     = make_float4(cc[0].f.y, cc[1].f.y, cc[2].f.y, cc[3].f.y);
            *(float4*)&outp[base + 4] = make_float4(cc[4].f.y, cc[5].f.y, cc[6].f.y, cc[7].f.y);
        }
    }
}

// ---------------- K5: g = out@fcg_w + b, GLU, +x, LayerNorm  (warp per row, fw in smem) ----------------
__global__ __launch_bounds__(256) void k_fin(const float* __restrict__ x,
                                             const float* __restrict__ fw,
                                             const float* __restrict__ fb,
                                             const float* __restrict__ lng,
                                             const float* __restrict__ lnb,
                                             float* __restrict__ y) {
    __shared__ __align__(16) float fws[64 * 128];
    __shared__ float outs[8][64];
    int tid = threadIdx.x;
    {
        const float4* fw4 = (const float4*)fw;
        float4* fs4 = (float4*)fws;
#pragma unroll
        for (int i = 0; i < 8; i++) fs4[tid + i * 256] = fw4[tid + i * 256];
    }
    int r0 = blockIdx.x * 8;
#pragma unroll
    for (int i = 0; i < 2; i++) {
        int idx = tid + i * 256;
        size_t g = (size_t)r0 * 64 + idx;
        outs[idx >> 6][idx & 63] = 0.25f * (g_outp[0][g] + g_outp[1][g] + g_outp[2][g] + g_outp[3][g]);
    }
    __syncthreads();
    int w = tid >> 5, lane = tid & 31;
    int row = r0 + w;
    const float* o = outs[w];
    float a0 = fb[lane], a1 = fb[lane + 32], b0 = fb[64 + lane], b1 = fb[96 + lane];
#pragma unroll 4
    for (int k = 0; k < 64; k++) {
        float xo = o[k];
        const float* wr = fws + k * 128;
        a0 = fmaf(xo, wr[lane], a0);
        a1 = fmaf(xo, wr[lane + 32], a1);
        b0 = fmaf(xo, wr[64 + lane], b0);
        b1 = fmaf(xo, wr[96 + lane], b1);
    }
    float g0 = a0 / (1.f + __expf(-b0));
    float g1 = a1 / (1.f + __expf(-b1));
    float y0 = g0 + x[(size_t)row * 64 + lane];
    float y1 = g1 + x[(size_t)row * 64 + lane + 32];
    float s1 = y0 + y1, s2 = y0 * y0 + y1 * y1;
#pragma unroll
    for (int off = 16; off; off >>= 1) {
        s1 += __shfl_xor_sync(0xffffffffu, s1, off);
        s2 += __shfl_xor_sync(0xffffffffu, s2, off);
    }
    float mu = s1 * (1.f / 64.f);
    float var = s2 * (1.f / 64.f) - mu * mu;
    float inv = rsqrtf(var + 1e-5f);
    y[(size_t)row * 64 + lane]      = (y0 - mu) * inv * lng[lane] + lnb[lane];
    y[(size_t)row * 64 + lane + 32] = (y1 - mu) * inv * lng[lane + 32] + lnb[lane + 32];
}

extern "C" void kernel_launch(void* const* d_in, const int* in_sizes, int n_in,
                              void* d_out, int out_size) {
    const float* x      = (const float*)d_in[0];
    const float* causal = (const float*)d_in[1];
    const float* W      = (const float*)d_in[2];
    const float* attw   = (const float*)d_in[3];
    const float* cw     = (const float*)d_in[4];
    const float* cb     = (const float*)d_in[5];
    const float* fcgw   = (const float*)d_in[6];
    const float* fcgb   = (const float*)d_in[7];
    const float* lng    = (const float*)d_in[8];
    const float* lnb    = (const float*)d_in[9];

    float* y = (float*)d_out;                       // y: B*N*D
    float* A = y + (size_t)BB * NF * DD;            // A: B*H*N*N

    k_xt  <<<1020, 256>>>(x, W);
    k_s   <<<2040, 256>>>(attw);
    k_cc  <<<510, 512>>>(causal, cw, cb);
    k_attn<<<dim3(32, 32), 512>>>(cw, A);
    k_av  <<<dim3(4, 32, 4), 128>>>(A);
    k_fin <<<2040, 256>>>(x, fcgw, fcgb, lng, lnb, y);
}

// round 13
// speedup vs baseline: 2.2770x; 1.0118x over previous
#include <cuda_runtime.h>
#include <cstddef>

#define NF 510
#define BB 32
#define HH 4
#define DD 64

// ---------------- scratch (__device__ globals; no allocation allowed) ----------------
__device__ float  g_xt[(size_t)BB*NF*256];        // xt[b][n][h*64+d]
__device__ float  g_si[BB*HH*NF];                 // s_i[b][h][n]
__device__ float  g_sj[BB*HH*NF];                 // s_j[b][h][n]
__device__ float4 g_cc[(size_t)NF*NF];            // 0.9*(conv3x3(causal, w[:,1]) + bias)
__device__ float  g_outp[4][(size_t)BB*NF*DD];    // per-head partial A_h @ xt_h

// ---- packed f32x2 helpers (FFMA2: 2 MACs / instruction) ----
__device__ __forceinline__ unsigned long long pk2(float v) {
    unsigned long long r;
    unsigned u = __float_as_uint(v);
    asm("mov.b64 %0, {%1, %1};" : "=l"(r) : "r"(u));
    return r;
}
__device__ __forceinline__ void ffma2(unsigned long long& d, unsigned long long a, unsigned long long b) {
    asm("fma.rn.f32x2 %0, %1, %2, %0;" : "+l"(d) : "l"(a), "l"(b));
}

// ---------------- K1: xt = x @ W   (16320x64 @ 64x256) ----------------
__global__ __launch_bounds__(256) void k_xt(const float* __restrict__ x,
                                            const float* __restrict__ W) {
    __shared__ __align__(16) float xs[16][64];
    int c = threadIdx.x;
    size_t base = (size_t)blockIdx.x * (16 * 64);
#pragma unroll
    for (int i = 0; i < 4; i++) {
        int idx = c + i * 256;
        xs[idx >> 6][idx & 63] = x[base + idx];
    }
    __syncthreads();
    float acc[16];
#pragma unroll
    for (int r = 0; r < 16; r++) acc[r] = 0.f;
    for (int kc = 0; kc < 16; kc++) {
        float w0 = W[(kc * 4 + 0) * 256 + c];
        float w1 = W[(kc * 4 + 1) * 256 + c];
        float w2 = W[(kc * 4 + 2) * 256 + c];
        float w3 = W[(kc * 4 + 3) * 256 + c];
#pragma unroll
        for (int r = 0; r < 16; r++) {
            float4 xv = *(const float4*)&xs[r][kc * 4];
            acc[r] = fmaf(xv.x, w0, acc[r]);
            acc[r] = fmaf(xv.y, w1, acc[r]);
            acc[r] = fmaf(xv.z, w2, acc[r]);
            acc[r] = fmaf(xv.w, w3, acc[r]);
        }
    }
    size_t ob = (size_t)blockIdx.x * (16 * 256);
#pragma unroll
    for (int r = 0; r < 16; r++) g_xt[ob + r * 256 + c] = acc[r];
}

// ---------------- K2: s_i, s_j (one warp per (b,n) row) ----------------
__global__ __launch_bounds__(256) void k_s(const float* __restrict__ attw) {
    __shared__ float aw[512];
    int tid = threadIdx.x;
    aw[tid] = attw[tid];
    aw[tid + 256] = attw[tid + 256];
    __syncthreads();
    int w = tid >> 5, lane = tid & 31;
    int row = blockIdx.x * 8 + w;
    const float* xr = g_xt + (size_t)row * 256;
    float xv[8];
#pragma unroll
    for (int j = 0; j < 8; j++) xv[j] = xr[lane + 32 * j];
    int b = row / NF, n = row % NF;
#pragma unroll
    for (int h = 0; h < 4; h++) {
        float si = xv[2*h] * aw[h*128 + lane] + xv[2*h+1] * aw[h*128 + 32 + lane];
        float sj = xv[2*h] * aw[h*128 + 64 + lane] + xv[2*h+1] * aw[h*128 + 96 + lane];
#pragma unroll
        for (int o = 16; o; o >>= 1) {
            si += __shfl_xor_sync(0xffffffffu, si, o);
            sj += __shfl_xor_sync(0xffffffffu, sj, o);
        }
        if (!lane) {
            g_si[(b * 4 + h) * NF + n] = si;
            g_sj[(b * 4 + h) * NF + n] = sj;
        }
    }
}

// ---------------- K2b: Cc = 0.9*(conv3x3(causal, w[:,1,:,:]) + bias), batch-invariant ----------------
__global__ __launch_bounds__(512) void k_cc(const float* __restrict__ causal,
                                            const float* __restrict__ cw,
                                            const float* __restrict__ cb) {
    __shared__ float cs[3][512];
    __shared__ float w1s[36];
    __shared__ float cbs[4];
    int m = threadIdx.x, n = blockIdx.x;
    if (m < 36) w1s[m] = 0.9f * cw[(m / 9) * 18 + 9 + (m % 9)];
    if (m < 4)  cbs[m] = 0.9f * cb[m];
#pragma unroll
    for (int ky = 0; ky < 3; ky++) {
        int rr = n + ky - 1;
        if (m < NF) cs[ky][m + 1] = (rr >= 0 && rr < NF) ? causal[rr * NF + m] : 0.f;
        else        cs[ky][m == NF ? 0 : 511] = 0.f;
    }
    __syncthreads();
    if (m < NF) {
        float c[9];
#pragma unroll
        for (int ky = 0; ky < 3; ky++)
#pragma unroll
            for (int kx = 0; kx < 3; kx++) c[ky * 3 + kx] = cs[ky][m + kx];
        float o[4];
#pragma unroll
        for (int h = 0; h < 4; h++) {
            float v = cbs[h];
#pragma unroll
            for (int j = 0; j < 9; j++) v = fmaf(w1s[h * 9 + j], c[j], v);
            o[h] = v;
        }
        g_cc[n * NF + m] = make_float4(o[0], o[1], o[2], o[3]);
    }
}

// ---------------- K3: warp-pair-per-row, e cached in registers, A written ONCE ----------------
// block = 512 thr = 16 warps = 8 rows x 2 head-slots (slot 0: h0,h1; slot 1: h2,h3).
__global__ __launch_bounds__(512, 2) void k_attn(const float* __restrict__ cw,
                                                 float* __restrict__ Aout) {
    __shared__ float amean[10][520];   // conv input rows r0-1 .. r0+8; col = m+1
    __shared__ float sjs[4][512];      // s_j per head (cols 510,511 = 0)
    __shared__ float sis[10][4];       // s_i rows r0-1 .. r0+8
    __shared__ float w0s[36];

    int tid = threadIdx.x;
    int b = blockIdx.y;
    int r0 = blockIdx.x * 8;
    int wid = tid >> 5, lane = tid & 31;
    int rt = wid >> 1;                 // row in tile 0..7
    int slot = wid & 1;                // head pair

#pragma unroll
    for (int h = 0; h < 4; h++)
        sjs[h][tid] = (tid < NF) ? g_sj[(b * 4 + h) * NF + tid] : 0.f;
    if (tid < 40) {
        int rr = tid >> 2, h = tid & 3;
        int row = r0 - 1 + rr;
        sis[rr][h] = ((unsigned)row < NF) ? g_si[(b * 4 + h) * NF + row] : 0.f;
    }
    if (tid < 36) w0s[tid] = 0.225f * cw[(tid / 9) * 18 + (tid % 9)];  // 0.9*0.25 folded
    __syncthreads();

    {
        float sjl[4];
#pragma unroll
        for (int h = 0; h < 4; h++) sjl[h] = sjs[h][tid];
        bool mok = tid < NF;
#pragma unroll
        for (int rr = 0; rr < 10; rr++) {
            int row = r0 - 1 + rr;
            float v = 0.f;
            if (mok && (unsigned)row < NF) {
#pragma unroll
                for (int h = 0; h < 4; h++) {
                    float t = sis[rr][h] + sjl[h];
                    v += fmaxf(t, 0.01f * t);
                }
            }
            amean[rr][tid + 1] = v;
        }
        if (tid < 10) { amean[tid][0] = 0.f; amean[tid][513] = 0.f; }
    }
    __syncthreads();

    int n = r0 + rt;
    if (n >= NF) return;

    int h0 = slot * 2;
    float si0 = sis[rt + 1][h0], si1 = sis[rt + 1][h0 + 1];
    const float* wh0 = &w0s[h0 * 9];
    const float* wh1 = &w0s[(h0 + 1) * 9];
    const float* ccp = (const float*)g_cc + ((size_t)n * NF) * 4 + slot * 2;  // + m*4

    float e0[16], e1[16];
    float sum0 = 0.f, sum1 = 0.f;
#pragma unroll
    for (int c = 0; c < 16; c++) {
        int m = c * 32 + lane;
        bool mval = m < NF;
        float t00 = amean[rt][m],     t01 = amean[rt][m + 1],     t02 = amean[rt][m + 2];
        float t10 = amean[rt + 1][m], t11 = amean[rt + 1][m + 1], t12 = amean[rt + 1][m + 2];
        float t20 = amean[rt + 2][m], t21 = amean[rt + 2][m + 1], t22 = amean[rt + 2][m + 2];
        float2 cc = make_float2(0.f, 0.f);
        if (mval) cc = *(const float2*)&ccp[(size_t)m * 4];
        float a0 = cc.x, a1 = cc.y;
        a0 = fmaf(wh0[0], t00, a0); a0 = fmaf(wh0[1], t01, a0); a0 = fmaf(wh0[2], t02, a0);
        a0 = fmaf(wh0[3], t10, a0); a0 = fmaf(wh0[4], t11, a0); a0 = fmaf(wh0[5], t12, a0);
        a0 = fmaf(wh0[6], t20, a0); a0 = fmaf(wh0[7], t21, a0); a0 = fmaf(wh0[8], t22, a0);
        a1 = fmaf(wh1[0], t00, a1); a1 = fmaf(wh1[1], t01, a1); a1 = fmaf(wh1[2], t02, a1);
        a1 = fmaf(wh1[3], t10, a1); a1 = fmaf(wh1[4], t11, a1); a1 = fmaf(wh1[5], t12, a1);
        a1 = fmaf(wh1[6], t20, a1); a1 = fmaf(wh1[7], t21, a1); a1 = fmaf(wh1[8], t22, a1);
        float tt0 = si0 + sjs[h0][m];
        float tt1 = si1 + sjs[h0 + 1][m];
        float lg0 = fmaf(0.1f, fmaxf(tt0, 0.01f * tt0), a0);
        float lg1 = fmaf(0.1f, fmaxf(tt1, 0.01f * tt1), a1);
        e0[c] = mval ? __expf(lg0) : 0.f;   // logits bounded far below fp32 exp overflow
        e1[c] = mval ? __expf(lg1) : 0.f;
        sum0 += e0[c]; sum1 += e1[c];
    }
#pragma unroll
    for (int o = 16; o; o >>= 1) {
        sum0 += __shfl_xor_sync(0xffffffffu, sum0, o);
        sum1 += __shfl_xor_sync(0xffffffffu, sum1, o);
    }
    float i0 = 1.0f / sum0, i1 = 1.0f / sum1;
    size_t base0 = ((size_t)(b * 4 + h0) * NF + n) * NF;
    size_t base1 = base0 + (size_t)NF * NF;
#pragma unroll
    for (int c = 0; c < 16; c++) {
        int m = c * 32 + lane;
        if (m < NF) {
            Aout[base0 + m] = e0[c] * i0;
            Aout[base1 + m] = e1[c] * i1;
        }
    }
}

// ---------------- K4: per-head partial = A_h @ xt_h  (tile 128x64, 8x8 microtile, FFMA2) ----------------
// grid (4 row-tiles, 32 batches, 4 heads) = 512 blocks, 128 threads.
__global__ __launch_bounds__(128) void k_av(const float* __restrict__ A) {
    __shared__ __align__(16) float As[16 * 132];   // [k][row], pitch 132
    __shared__ __align__(16) float Bs[16 * 68];    // [k][col], pitch 68
    int b = blockIdx.y;
    int h = blockIdx.z;
    int r0 = blockIdx.x * 128;
    int nvalid = NF - r0; if (nvalid > 128) nvalid = 128;
    int tid = threadIdx.x;
    int tx = tid & 7, ty = tid >> 3;
    int la_k = tid & 15, la_r0 = (tid >> 4) * 16;
    int lb_c = tid & 63, lb_k0 = (tid >> 6) * 8;

    const float* Ab = A + ((size_t)(b * 4 + h) * NF + r0) * NF;
    const float* Xb = g_xt + (size_t)b * NF * 256 + h * 64;

    unsigned long long acc2[4][8];
#pragma unroll
    for (int i = 0; i < 4; i++)
#pragma unroll
        for (int j = 0; j < 8; j++) acc2[i][j] = 0ull;

    float ra[16], rb[8];
#pragma unroll
    for (int i = 0; i < 16; i++) {
        int row = la_r0 + i;
        ra[i] = (row < nvalid) ? Ab[(size_t)row * NF + la_k] : 0.f;
    }
#pragma unroll
    for (int i = 0; i < 8; i++)
        rb[i] = Xb[(size_t)(lb_k0 + i) * 256 + lb_c];

    for (int it = 0; it < 32; it++) {
#pragma unroll
        for (int i = 0; i < 16; i++) As[la_k * 132 + la_r0 + i] = ra[i];
#pragma unroll
        for (int i = 0; i < 8; i++) Bs[(lb_k0 + i) * 68 + lb_c] = rb[i];
        __syncthreads();
        if (it + 1 < 32) {
            int k0 = (it + 1) * 16;
#pragma unroll
            for (int i = 0; i < 16; i++) {
                int row = la_r0 + i;
                ra[i] = (row < nvalid && k0 + la_k < NF) ? Ab[(size_t)row * NF + k0 + la_k] : 0.f;
            }
#pragma unroll
            for (int i = 0; i < 8; i++) {
                int k = k0 + lb_k0 + i;
                rb[i] = (k < NF) ? Xb[(size_t)k * 256 + lb_c] : 0.f;
            }
        }
        int ty8 = ty * 8, tx8 = tx * 8;
#pragma unroll
        for (int kk = 0; kk < 16; kk++) {
            ulonglong2 aA = *(const ulonglong2*)&As[kk * 132 + ty8];
            ulonglong2 aB = *(const ulonglong2*)&As[kk * 132 + ty8 + 4];
            float4 bv0 = *(const float4*)&Bs[kk * 68 + tx8];
            float4 bv1 = *(const float4*)&Bs[kk * 68 + tx8 + 4];
            unsigned long long bp[8] = {pk2(bv0.x), pk2(bv0.y), pk2(bv0.z), pk2(bv0.w),
                                        pk2(bv1.x), pk2(bv1.y), pk2(bv1.z), pk2(bv1.w)};
#pragma unroll
            for (int c = 0; c < 8; c++) {
                ffma2(acc2[0][c], aA.x, bp[c]);
                ffma2(acc2[1][c], aA.y, bp[c]);
                ffma2(acc2[2][c], aB.x, bp[c]);
                ffma2(acc2[3][c], aB.y, bp[c]);
            }
        }
        __syncthreads();
    }
    float* outp = g_outp[h];
#pragma unroll
    for (int j = 0; j < 4; j++) {
        union { unsigned long long u; float2 f; } cc[8];
#pragma unroll
        for (int c = 0; c < 8; c++) cc[c].u = acc2[j][c];
        int row0 = ty * 8 + 2 * j;
        if (row0 < nvalid) {
            size_t base = ((size_t)(b * NF) + r0 + row0) * 64 + tx * 8;
            *(float4*)&outp[base]     = make_float4(cc[0].f.x, cc[1].f.x, cc[2].f.x, cc[3].f.x);
            *(float4*)&outp[base + 4] = make_float4(cc[4].f.x, cc[5].f.x, cc[6].f.x, cc[7].f.x);
        }
        if (row0 + 1 < nvalid) {
            size_t base = ((size_t)(b * NF) + r0 + row0 + 1) * 64 + tx * 8;
            *(float4*)&outp[base]     = make_float4(cc[0].f.y, cc[1].f.y, cc[2].f.y, cc[3].f.y);
            *(float4*)&outp[base + 4] = make_float4(cc[4].f.y, cc[5].f.y, cc[6].f.y, cc[7].f.y);
        }
    }
}

// ---------------- K5: g = out@fcg_w + b, GLU, +x, LayerNorm  (warp per row, fw in smem) ----------------
__global__ __launch_bounds__(256) void k_fin(const float* __restrict__ x,
                                             const float* __restrict__ fw,
                                             const float* __restrict__ fb,
                                             const float* __restrict__ lng,
                                             const float* __restrict__ lnb,
                                             float* __restrict__ y) {
    __shared__ __align__(16) float fws[64 * 128];
    __shared__ float outs[8][64];
    int tid = threadIdx.x;
    {
        const float4* fw4 = (const float4*)fw;
        float4* fs4 = (float4*)fws;
#pragma unroll
        for (int i = 0; i < 8; i++) fs4[tid + i * 256] = fw4[tid + i * 256];
    }
    int r0 = blockIdx.x * 8;
#pragma unroll
    for (int i = 0; i < 2; i++) {
        int idx = tid + i * 256;
        size_t g = (size_t)r0 * 64 + idx;
        outs[idx >> 6][idx & 63] = 0.25f * (g_outp[0][g] + g_outp[1][g] + g_outp[2][g] + g_outp[3][g]);
    }
    __syncthreads();
    int w = tid >> 5, lane = tid & 31;
    int row = r0 + w;
    const float* o = outs[w];
    float a0 = fb[lane], a1 = fb[lane + 32], b0 = fb[64 + lane], b1 = fb[96 + lane];
#pragma unroll 4
    for (int k = 0; k < 64; k++) {
        float xo = o[k];
        const float* wr = fws + k * 128;
        a0 = fmaf(xo, wr[lane], a0);
        a1 = fmaf(xo, wr[lane + 32], a1);
        b0 = fmaf(xo, wr[64 + lane], b0);
        b1 = fmaf(xo, wr[96 + lane], b1);
    }
    float g0 = a0 / (1.f + __expf(-b0));
    float g1 = a1 / (1.f + __expf(-b1));
    float y0 = g0 + x[(size_t)row * 64 + lane];
    float y1 = g1 + x[(size_t)row * 64 + lane + 32];
    float s1 = y0 + y1, s2 = y0 * y0 + y1 * y1;
#pragma unroll
    for (int off = 16; off; off >>= 1) {
        s1 += __shfl_xor_sync(0xffffffffu, s1, off);
        s2 += __shfl_xor_sync(0xffffffffu, s2, off);
    }
    float mu = s1 * (1.f / 64.f);
    float var = s2 * (1.f / 64.f) - mu * mu;
    float inv = rsqrtf(var + 1e-5f);
    y[(size_t)row * 64 + lane]      = (y0 - mu) * inv * lng[lane] + lnb[lane];
    y[(size_t)row * 64 + lane + 32] = (y1 - mu) * inv * lng[lane + 32] + lnb[lane + 32];
}

extern "C" void kernel_launch(void* const* d_in, const int* in_sizes, int n_in,
                              void* d_out, int out_size) {
    const float* x      = (const float*)d_in[0];
    const float* causal = (const float*)d_in[1];
    const float* W      = (const float*)d_in[2];
    const float* attw   = (const float*)d_in[3];
    const float* cw     = (const float*)d_in[4];
    const float* cb     = (const float*)d_in[5];
    const float* fcgw   = (const float*)d_in[6];
    const float* fcgb   = (const float*)d_in[7];
    const float* lng    = (const float*)d_in[8];
    const float* lnb    = (const float*)d_in[9];

    float* y = (float*)d_out;                       // y: B*N*D
    float* A = y + (size_t)BB * NF * DD;            // A: B*H*N*N

    k_xt  <<<1020, 256>>>(x, W);
    k_s   <<<2040, 256>>>(attw);
    k_cc  <<<510, 512>>>(causal, cw, cb);
    k_attn<<<dim3(64, 32), 512>>>(cw, A);
    k_av  <<<dim3(4, 32, 4), 128>>>(A);
    k_fin <<<2040, 256>>>(x, fcgw, fcgb, lng, lnb, y);
}